// round 7
// baseline (speedup 1.0000x reference)
#include <cuda_runtime.h>
#include <cuda_bf16.h>

#define T_TOKENS 16384
#define H_DIM    2880
#define E_EXP    32
#define TOPK     4
#define KSPLIT   4
#define KPW      (H_DIM / KSPLIT)    // 720 per warp
#define NK16     (KPW / 16)          // 45 k16 steps per warp

__device__ __nv_bfloat16 g_wh[E_EXP * H_DIM];   // 184 KB
__device__ __nv_bfloat16 g_wl[E_EXP * H_DIM];   // 184 KB

// ---------------- kernel 0: convert W fp32 -> bf16 hi/lo planes ----------------
__global__ __launch_bounds__(256)
void convert_w(const float* __restrict__ w)
{
    int i = blockIdx.x * 256 + threadIdx.x;
    if (i < E_EXP * H_DIM) {
        float v = w[i];
        __nv_bfloat16 h = __float2bfloat16_rn(v);
        g_wh[i] = h;
        g_wl[i] = __float2bfloat16_rn(v - __bfloat162float(h));
    }
}

// pack float2 -> bf16x2 hi reg + lo reg (lo = exact residual re-rounded)
__device__ __forceinline__ void cvt_hl(float2 f, unsigned& h, unsigned& l)
{
    asm("cvt.rn.bf16x2.f32 %0, %1, %2;" : "=r"(h) : "f"(f.y), "f"(f.x));
    float h0 = __uint_as_float(h << 16);
    float h1 = __uint_as_float(h & 0xffff0000u);
    asm("cvt.rn.bf16x2.f32 %0, %1, %2;" : "=r"(l) : "f"(f.y - h1), "f"(f.x - h0));
}

__device__ __forceinline__ void hmma(float* d, const unsigned* a, unsigned b0, unsigned b1)
{
    asm volatile(
        "mma.sync.aligned.m16n8k16.row.col.f32.bf16.bf16.f32 "
        "{%0,%1,%2,%3}, {%4,%5,%6,%7}, {%8,%9}, {%0,%1,%2,%3};"
        : "+f"(d[0]), "+f"(d[1]), "+f"(d[2]), "+f"(d[3])
        : "r"(a[0]), "r"(a[1]), "r"(a[2]), "r"(a[3]), "r"(b0), "r"(b1));
}

// ---------------- kernel 1: fused gate (GEMM on tensor pipe + top-4 + softmax) ----------------
__global__ __launch_bounds__(128)
void gate_mma(const float* __restrict__ x,
              const float* __restrict__ bias,
              float* __restrict__ out)
{
    __shared__ float part[KSPLIT][16][E_EXP + 1];   // per-warp partial logits

    const int tid  = threadIdx.x;
    const int warp = tid >> 5;
    const int lane = tid & 31;
    const int gid  = lane >> 2;      // 0..7 : token row (and row+8)
    const int tig  = lane & 3;       // 0..3 : k sub-offset / expert sub-col
    const int t0   = blockIdx.x * 16;
    const int kb   = warp * KPW;     // this warp's K range

    // A source rows (fragment-direct): row gid and gid+8
    const float* xr0 = x + (size_t)(t0 + gid) * H_DIM + kb + tig * 2;
    const float* xr1 = xr0 + (size_t)8 * H_DIM;

    // B sources: experts 8j + gid, bf16 planes
    const __nv_bfloat16* whp = g_wh + (size_t)gid * H_DIM + kb + tig * 2;
    const __nv_bfloat16* wlp = g_wl + (size_t)gid * H_DIM + kb + tig * 2;

    float acc[4][4];
    #pragma unroll
    for (int j = 0; j < 4; ++j)
        #pragma unroll
        for (int q = 0; q < 4; ++q) acc[j][q] = 0.0f;

    #pragma unroll 3
    for (int kt = 0; kt < NK16; ++kt) {
        const int ko = kt * 16;

        // ---- A fragment: fp32 loads + in-register hi/lo split ----
        float2 f00 = *reinterpret_cast<const float2*>(xr0 + ko);        // row0, k-low
        float2 f10 = *reinterpret_cast<const float2*>(xr1 + ko);        // row1, k-low
        float2 f01 = *reinterpret_cast<const float2*>(xr0 + ko + 8);    // row0, k-high
        float2 f11 = *reinterpret_cast<const float2*>(xr1 + ko + 8);    // row1, k-high

        unsigned ah[4], al[4];
        cvt_hl(f00, ah[0], al[0]);
        cvt_hl(f10, ah[1], al[1]);
        cvt_hl(f01, ah[2], al[2]);
        cvt_hl(f11, ah[3], al[3]);

        // ---- B fragments: pre-converted bf16 (L1/L2 hot) ----
        unsigned bh0[4], bh1[4], bl0[4], bl1[4];
        #pragma unroll
        for (int j = 0; j < 4; ++j) {
            const size_t eo = (size_t)(8 * j) * H_DIM + ko;
            bh0[j] = *reinterpret_cast<const unsigned*>(whp + eo);
            bh1[j] = *reinterpret_cast<const unsigned*>(whp + eo + 8);
            bl0[j] = *reinterpret_cast<const unsigned*>(wlp + eo);
            bl1[j] = *reinterpret_cast<const unsigned*>(wlp + eo + 8);
        }

        // ---- 3-term emulated fp32 MMA: AhBh + AlBh + AhBl ----
        #pragma unroll
        for (int j = 0; j < 4; ++j) {
            hmma(acc[j], ah, bh0[j], bh1[j]);
            hmma(acc[j], al, bh0[j], bh1[j]);
            hmma(acc[j], ah, bl0[j], bl1[j]);
        }
    }

    // ---- stage partials: c0,c1 -> row gid; c2,c3 -> row gid+8; cols 8j+tig*2{,+1} ----
    #pragma unroll
    for (int j = 0; j < 4; ++j) {
        const int e = 8 * j + tig * 2;
        part[warp][gid][e]         = acc[j][0];
        part[warp][gid][e + 1]     = acc[j][1];
        part[warp][gid + 8][e]     = acc[j][2];
        part[warp][gid + 8][e + 1] = acc[j][3];
    }
    __syncthreads();

    // ---- reduce across K-split warps + bias + top-4 + softmax ----
    if (tid < 16) {
        const int t = tid;
        float bv0 = -1e30f, bv1 = -1e30f, bv2 = -1e30f, bv3 = -1e30f;
        int   bi0 = 0, bi1 = 0, bi2 = 0, bi3 = 0;
        #pragma unroll
        for (int e = 0; e < E_EXP; ++e) {
            float lv = part[0][t][e] + part[1][t][e] + part[2][t][e] + part[3][t][e]
                     + bias[e];
            if (lv > bv3) {
                if (lv > bv0) {
                    bv3 = bv2; bi3 = bi2; bv2 = bv1; bi2 = bi1; bv1 = bv0; bi1 = bi0;
                    bv0 = lv;  bi0 = e;
                } else if (lv > bv1) {
                    bv3 = bv2; bi3 = bi2; bv2 = bv1; bi2 = bi1;
                    bv1 = lv;  bi1 = e;
                } else if (lv > bv2) {
                    bv3 = bv2; bi3 = bi2;
                    bv2 = lv;  bi2 = e;
                } else {
                    bv3 = lv;  bi3 = e;
                }
            }
        }
        float e0 = 1.0f;
        float e1 = expf(bv1 - bv0);
        float e2 = expf(bv2 - bv0);
        float e3 = expf(bv3 - bv0);
        float inv = 1.0f / (e0 + e1 + e2 + e3);

        const int gt = t0 + t;
        float* oi = out + (size_t)gt * TOPK;
        float* ow = out + (size_t)T_TOKENS * TOPK + (size_t)gt * TOPK;
        oi[0] = (float)bi0; oi[1] = (float)bi1; oi[2] = (float)bi2; oi[3] = (float)bi3;
        ow[0] = e0 * inv;   ow[1] = e1 * inv;   ow[2] = e2 * inv;   ow[3] = e3 * inv;
    }
}

extern "C" void kernel_launch(void* const* d_in, const int* in_sizes, int n_in,
                              void* d_out, int out_size)
{
    const float* x    = (const float*)d_in[0];  // [4,4096,2880] f32
    const float* w    = (const float*)d_in[1];  // [32,2880] f32
    const float* bias = (const float*)d_in[2];  // [32] f32
    float* out = (float*)d_out;

    convert_w<<<(E_EXP * H_DIM + 255) / 256, 256>>>(w);
    gate_mma<<<T_TOKENS / 16, 128>>>(x, bias, out);   // 1024 CTAs x 4 warps
}

// round 8
// speedup vs baseline: 1.5549x; 1.5549x over previous
#include <cuda_runtime.h>
#include <cuda_bf16.h>

#define T_TOKENS 16384
#define H_DIM    2880
#define E_EXP    32
#define TOPK     4
#define BM       64
#define NK16     (H_DIM / 16)      // 180 k-steps
#define NTHREADS 128

// W bf16 hi/lo planes, k-INTERLEAVED within each 16-group so one LDS.64 = (b0,b1) frag:
// pos(k) within 16: {0,1,8,9, 2,3,10,11, 4,5,12,13, 6,7,14,15}
__device__ __nv_bfloat16 g_wh[E_EXP * H_DIM];
__device__ __nv_bfloat16 g_wl[E_EXP * H_DIM];

__global__ __launch_bounds__(256)
void convert_w(const float* __restrict__ w)
{
    int i = blockIdx.x * 256 + threadIdx.x;
    if (i < E_EXP * H_DIM) {
        int k   = i % H_DIM;
        int kb  = k & ~15;
        int k16 = k & 15;
        int pos = ((k16 & 7) >> 1) * 4 + ((k16 >> 3) << 1) + (k16 & 1);
        int j   = i - k + kb + pos;     // interleaved destination
        float v = w[i];
        __nv_bfloat16 h = __float2bfloat16_rn(v);
        g_wh[j] = h;
        g_wl[j] = __float2bfloat16_rn(v - __bfloat162float(h));
    }
}

__device__ __forceinline__ unsigned smem_u32(const void* p) {
    return (unsigned)__cvta_generic_to_shared(p);
}
__device__ __forceinline__ void cp16(unsigned dst, const void* src) {
    asm volatile("cp.async.cg.shared.global [%0], [%1], 16;" :: "r"(dst), "l"(src));
}
__device__ __forceinline__ void cp_commit() {
    asm volatile("cp.async.commit_group;");
}
template <int N>
__device__ __forceinline__ void cp_wait() {
    asm volatile("cp.async.wait_group %0;" :: "n"(N));
}
__device__ __forceinline__ void cvt_hl(float2 f, unsigned& h, unsigned& l)
{
    asm("cvt.rn.bf16x2.f32 %0, %1, %2;" : "=r"(h) : "f"(f.y), "f"(f.x));
    float h0 = __uint_as_float(h << 16);
    float h1 = __uint_as_float(h & 0xffff0000u);
    asm("cvt.rn.bf16x2.f32 %0, %1, %2;" : "=r"(l) : "f"(f.y - h1), "f"(f.x - h0));
}
__device__ __forceinline__ void hmma(float* d, const unsigned* a, unsigned b0, unsigned b1)
{
    asm volatile(
        "mma.sync.aligned.m16n8k16.row.col.f32.bf16.bf16.f32 "
        "{%0,%1,%2,%3}, {%4,%5,%6,%7}, {%8,%9}, {%0,%1,%2,%3};"
        : "+f"(d[0]), "+f"(d[1]), "+f"(d[2]), "+f"(d[3])
        : "r"(a[0]), "r"(a[1]), "r"(a[2]), "r"(a[3]), "r"(b0), "r"(b1));
}

__global__ __launch_bounds__(NTHREADS, 4)
void gate_mma(const float* __restrict__ x,
              const float* __restrict__ bias,
              float* __restrict__ out)
{
    // per stage: x tile [64 tok][16 k] fp32, rows 64B, chunk-swizzled (c ^= row&2)
    //            W tile [2 planes][32 e][32B interleaved-k]
    __shared__ __align__(16) char xsm[3][BM * 64];      // 12288 B
    __shared__ __align__(16) char wsm[3][2 * E_EXP * 32]; // 6144 B

    const int tid  = threadIdx.x;
    const int warp = tid >> 5;
    const int lane = tid & 31;
    const int gid  = lane >> 2;       // 0..7
    const int tig  = lane & 3;        // 0..3
    const int t0   = blockIdx.x * BM;
    const int wo   = warp * 16;       // warp token offset

    // ---- staging maps (all cp.async) ----
    // x: 256 chunks/stage: thread -> token tid>>1, chunks c = (tid&1)*2 + {0,1}
    const int stok = tid >> 1;
    const int sc0  = (tid & 1) * 2;
    const float* xg = x + (size_t)(t0 + stok) * H_DIM + sc0 * 4;
    unsigned xd[3][2];
    #pragma unroll
    for (int b = 0; b < 3; ++b) {
        xd[b][0] = smem_u32(&xsm[b][stok * 64 + ((sc0)     ^ (stok & 2)) * 16]);
        xd[b][1] = smem_u32(&xsm[b][stok * 64 + ((sc0 + 1) ^ (stok & 2)) * 16]);
    }
    // w: 128 chunks/stage: plane = tid>>6, e = (tid>>1)&31, half = tid&1
    const int spl = tid >> 6, se = (tid >> 1) & 31, sh = tid & 1;
    const __nv_bfloat16* wg =
        (spl ? g_wl : g_wh) + (size_t)se * H_DIM + sh * 8;
    unsigned wd[3];
    #pragma unroll
    for (int b = 0; b < 3; ++b)
        wd[b] = smem_u32(&wsm[b][spl * 1024 + se * 32 + sh * 16]);

    auto stage = [&](int kt, int b) {
        const size_t ko = (size_t)kt * 16;
        cp16(xd[b][0], xg + ko);
        cp16(xd[b][1], xg + ko + 4);
        cp16(wd[b], wg + ko);
        cp_commit();
    };

    // ---- compute-side smem addresses ----
    const int r0 = wo + gid, r1 = wo + gid + 8;
    const int cl = tig >> 1;                 // k-low chunk
    const int off = (tig & 1) * 8;
    const int a00 = r0 * 64 + ((cl)     ^ (gid & 2)) * 16 + off;   // row0 k-lo
    const int a10 = r1 * 64 + ((cl)     ^ (gid & 2)) * 16 + off;   // row1 k-lo
    const int a01 = r0 * 64 + ((cl + 2) ^ (gid & 2)) * 16 + off;   // row0 k-hi
    const int a11 = r1 * 64 + ((cl + 2) ^ (gid & 2)) * 16 + off;   // row1 k-hi

    float acc[4][4];
    #pragma unroll
    for (int j = 0; j < 4; ++j)
        #pragma unroll
        for (int q = 0; q < 4; ++q) acc[j][q] = 0.0f;

    stage(0, 0);
    stage(1, 1);

    #pragma unroll 2
    for (int kt = 0; kt < NK16; ++kt) {
        if (kt + 1 < NK16) { cp_wait<1>(); } else { cp_wait<0>(); }
        __syncthreads();
        if (kt + 2 < NK16) stage(kt + 2, (kt + 2) % 3);

        const char* xb = xsm[kt % 3];
        const char* wb = wsm[kt % 3];

        // A: 4 LDS.64 + hi/lo split
        float2 f00 = *reinterpret_cast<const float2*>(xb + a00);
        float2 f10 = *reinterpret_cast<const float2*>(xb + a10);
        float2 f01 = *reinterpret_cast<const float2*>(xb + a01);
        float2 f11 = *reinterpret_cast<const float2*>(xb + a11);
        unsigned ah[4], al[4];
        cvt_hl(f00, ah[0], al[0]);
        cvt_hl(f10, ah[1], al[1]);
        cvt_hl(f01, ah[2], al[2]);
        cvt_hl(f11, ah[3], al[3]);

        // B: 8 LDS.64 (one per j per plane), interleaved layout -> (b0,b1) direct
        #pragma unroll
        for (int j = 0; j < 4; ++j) {
            const int e = 8 * j + gid;
            uint2 bh = *reinterpret_cast<const uint2*>(wb + e * 32 + tig * 8);
            uint2 bl = *reinterpret_cast<const uint2*>(wb + 1024 + e * 32 + tig * 8);
            hmma(acc[j], ah, bh.x, bh.y);
            hmma(acc[j], al, bh.x, bh.y);
            hmma(acc[j], ah, bl.x, bl.y);
        }
    }
    __syncthreads();

    // ---- logits to smem (alias xsm), top-4 + softmax ----
    float (*lg)[E_EXP + 1] = reinterpret_cast<float (*)[E_EXP + 1]>(&xsm[0][0]);
    #pragma unroll
    for (int j = 0; j < 4; ++j) {
        const int e = 8 * j + 2 * tig;
        lg[wo + gid][e]         = acc[j][0];
        lg[wo + gid][e + 1]     = acc[j][1];
        lg[wo + gid + 8][e]     = acc[j][2];
        lg[wo + gid + 8][e + 1] = acc[j][3];
    }
    __syncthreads();

    if (tid < BM) {
        const int t = tid;
        float bv0 = -1e30f, bv1 = -1e30f, bv2 = -1e30f, bv3 = -1e30f;
        int   bi0 = 0, bi1 = 0, bi2 = 0, bi3 = 0;
        #pragma unroll
        for (int e = 0; e < E_EXP; ++e) {
            float lv = lg[t][e] + bias[e];
            if (lv > bv3) {
                if (lv > bv0) {
                    bv3 = bv2; bi3 = bi2; bv2 = bv1; bi2 = bi1; bv1 = bv0; bi1 = bi0;
                    bv0 = lv;  bi0 = e;
                } else if (lv > bv1) {
                    bv3 = bv2; bi3 = bi2; bv2 = bv1; bi2 = bi1;
                    bv1 = lv;  bi1 = e;
                } else if (lv > bv2) {
                    bv3 = bv2; bi3 = bi2;
                    bv2 = lv;  bi2 = e;
                } else {
                    bv3 = lv;  bi3 = e;
                }
            }
        }
        float e0 = 1.0f;
        float e1 = expf(bv1 - bv0);
        float e2 = expf(bv2 - bv0);
        float e3 = expf(bv3 - bv0);
        float inv = 1.0f / (e0 + e1 + e2 + e3);

        const int gt = t0 + t;
        float* oi = out + (size_t)gt * TOPK;
        float* ow = out + (size_t)T_TOKENS * TOPK + (size_t)gt * TOPK;
        oi[0] = (float)bi0; oi[1] = (float)bi1; oi[2] = (float)bi2; oi[3] = (float)bi3;
        ow[0] = e0 * inv;   ow[1] = e1 * inv;   ow[2] = e2 * inv;   ow[3] = e3 * inv;
    }
}

extern "C" void kernel_launch(void* const* d_in, const int* in_sizes, int n_in,
                              void* d_out, int out_size)
{
    const float* x    = (const float*)d_in[0];  // [4,4096,2880] f32
    const float* w    = (const float*)d_in[1];  // [32,2880] f32
    const float* bias = (const float*)d_in[2];  // [32] f32
    float* out = (float*)d_out;

    convert_w<<<(E_EXP * H_DIM + 255) / 256, 256>>>(w);
    gate_mma<<<T_TOKENS / BM, NTHREADS>>>(x, bias, out);   // 256 CTAs x 4 warps
}

// round 9
// speedup vs baseline: 2.6634x; 1.7129x over previous
#include <cuda_runtime.h>
#include <cuda_bf16.h>

#define T_TOKENS 16384
#define H_DIM    2880
#define E_EXP    32
#define TOPK     4
#define BM       64
#define KS       64                 // k per stage
#define NSTAGE   (H_DIM / KS)       // 45
#define NTHREADS 128

// W bf16 hi/lo planes, k-INTERLEAVED within each 16-group so one LDS.64 = (b0,b1) frag:
// pos(k) within 16: {0,1,8,9, 2,3,10,11, 4,5,12,13, 6,7,14,15}
__device__ __nv_bfloat16 g_wh[E_EXP * H_DIM];
__device__ __nv_bfloat16 g_wl[E_EXP * H_DIM];

__global__ __launch_bounds__(256)
void convert_w(const float* __restrict__ w)
{
    int i = blockIdx.x * 256 + threadIdx.x;
    if (i < E_EXP * H_DIM) {
        int k   = i % H_DIM;
        int kb  = k & ~15;
        int k16 = k & 15;
        int pos = ((k16 & 7) >> 1) * 4 + ((k16 >> 3) << 1) + (k16 & 1);
        int j   = i - k + kb + pos;
        float v = w[i];
        __nv_bfloat16 h = __float2bfloat16_rn(v);
        g_wh[j] = h;
        g_wl[j] = __float2bfloat16_rn(v - __bfloat162float(h));
    }
}

__device__ __forceinline__ unsigned smem_u32(const void* p) {
    return (unsigned)__cvta_generic_to_shared(p);
}
__device__ __forceinline__ void cp16(unsigned dst, const void* src) {
    asm volatile("cp.async.cg.shared.global [%0], [%1], 16;" :: "r"(dst), "l"(src));
}
__device__ __forceinline__ void cp_commit() {
    asm volatile("cp.async.commit_group;");
}
template <int N>
__device__ __forceinline__ void cp_wait() {
    asm volatile("cp.async.wait_group %0;" :: "n"(N));
}
__device__ __forceinline__ void cvt_hl(float2 f, unsigned& h, unsigned& l)
{
    asm("cvt.rn.bf16x2.f32 %0, %1, %2;" : "=r"(h) : "f"(f.y), "f"(f.x));
    float h0 = __uint_as_float(h << 16);
    float h1 = __uint_as_float(h & 0xffff0000u);
    asm("cvt.rn.bf16x2.f32 %0, %1, %2;" : "=r"(l) : "f"(f.y - h1), "f"(f.x - h0));
}
__device__ __forceinline__ void hmma(float* d, const unsigned* a, unsigned b0, unsigned b1)
{
    asm volatile(
        "mma.sync.aligned.m16n8k16.row.col.f32.bf16.bf16.f32 "
        "{%0,%1,%2,%3}, {%4,%5,%6,%7}, {%8,%9}, {%0,%1,%2,%3};"
        : "+f"(d[0]), "+f"(d[1]), "+f"(d[2]), "+f"(d[3])
        : "r"(a[0]), "r"(a[1]), "r"(a[2]), "r"(a[3]), "r"(b0), "r"(b1));
}

__global__ __launch_bounds__(NTHREADS, 3)
void gate_mma(const float* __restrict__ x,
              const float* __restrict__ bias,
              float* __restrict__ out)
{
    // per stage: x [64 tok][64 k] fp32, 256B rows, chunk-swizzled ch^=(tok&7)
    //            w [2 planes][32 e][64 k interleaved bf16], 128B rows, ch^=(e&7)
    __shared__ __align__(16) char xsm[3][BM * 256];        // 48 KB
    __shared__ __align__(16) char wsm[3][2 * E_EXP * 128]; // 24 KB

    const int tid  = threadIdx.x;
    const int warp = tid >> 5;
    const int lane = tid & 31;
    const int gid  = lane >> 2;       // 0..7
    const int tig  = lane & 3;        // 0..3
    const int t0   = blockIdx.x * BM;
    const int wo   = warp * 16;       // warp token offset

    // ---- staging maps ----
    // x: 1024 chunks/stage. id = tid + 128*i (i<8): tok=id>>4, kc=id&15
    const float* xsrc[8];
    int xdo[8];
    #pragma unroll
    for (int i = 0; i < 8; ++i) {
        int id  = tid + 128 * i;
        int tok = id >> 4, kc = id & 15;
        xsrc[i] = x + (size_t)(t0 + tok) * H_DIM + kc * 4;
        xdo[i]  = tok * 256 + ((kc ^ (tok & 7)) << 4);
    }
    // w: 512 chunks/stage. id = tid + 128*i (i<4): plane=id>>8, e=(id>>3)&31, kc=id&7
    const __nv_bfloat16* wsrc[4];
    int wdo[4];
    #pragma unroll
    for (int i = 0; i < 4; ++i) {
        int id = tid + 128 * i;
        int pl = id >> 8, e = (id >> 3) & 31, kc = id & 7;
        wsrc[i] = (pl ? g_wl : g_wh) + (size_t)e * H_DIM + kc * 8;
        wdo[i]  = pl * 4096 + e * 128 + ((kc ^ (e & 7)) << 4);
    }

    auto stage = [&](int kt, int b) {
        const size_t ko = (size_t)kt * KS;
        #pragma unroll
        for (int i = 0; i < 8; ++i)
            cp16(smem_u32(&xsm[b][xdo[i]]), xsrc[i] + ko);
        #pragma unroll
        for (int i = 0; i < 4; ++i)
            cp16(smem_u32(&wsm[b][wdo[i]]), wsrc[i] + ko);
        cp_commit();
    };

    // ---- compute-side address precompute ----
    // A: rows r0=wo+gid, r1=r0+8; per ks: chunks ks*4+cl and ks*4+cl+2, cl=tig>>1,
    //    swizzle ^gid (== row&7 for both rows), sub-byte (tig&1)*8
    const int r0 = wo + gid, r1 = r0 + 8;
    const int cl = tig >> 1;
    const int sub = (tig & 1) * 8;
    // B: row e=8j+gid (128B), chunk ks*2+(tig>>1) ^ gid, sub (tig&1)*8
    float acc[4][4];
    #pragma unroll
    for (int j = 0; j < 4; ++j)
        #pragma unroll
        for (int q = 0; q < 4; ++q) acc[j][q] = 0.0f;

    stage(0, 0);
    stage(1, 1);

    for (int kt = 0; kt < NSTAGE; ++kt) {
        if (kt + 1 < NSTAGE) { cp_wait<1>(); } else { cp_wait<0>(); }
        __syncthreads();
        if (kt + 2 < NSTAGE) stage(kt + 2, (kt + 2) % 3);

        const char* xb = xsm[kt % 3];
        const char* wb = wsm[kt % 3];

        #pragma unroll
        for (int ks = 0; ks < 4; ++ks) {
            const int cA0 = (ks * 4 + cl) ^ gid;
            const int cA1 = (ks * 4 + cl + 2) ^ gid;
            float2 f00 = *reinterpret_cast<const float2*>(xb + r0 * 256 + cA0 * 16 + sub);
            float2 f10 = *reinterpret_cast<const float2*>(xb + r1 * 256 + cA0 * 16 + sub);
            float2 f01 = *reinterpret_cast<const float2*>(xb + r0 * 256 + cA1 * 16 + sub);
            float2 f11 = *reinterpret_cast<const float2*>(xb + r1 * 256 + cA1 * 16 + sub);
            unsigned ah[4], al[4];
            cvt_hl(f00, ah[0], al[0]);
            cvt_hl(f10, ah[1], al[1]);
            cvt_hl(f01, ah[2], al[2]);
            cvt_hl(f11, ah[3], al[3]);

            const int cB = ((ks * 2 + cl) ^ gid) * 16 + sub;
            #pragma unroll
            for (int j = 0; j < 4; ++j) {
                const int e = 8 * j + gid;
                uint2 bh = *reinterpret_cast<const uint2*>(wb + e * 128 + cB);
                uint2 bl = *reinterpret_cast<const uint2*>(wb + 4096 + e * 128 + cB);
                hmma(acc[j], ah, bh.x, bh.y);
                hmma(acc[j], al, bh.x, bh.y);
                hmma(acc[j], ah, bl.x, bl.y);
            }
        }
    }
    __syncthreads();

    // ---- logits to smem (alias xsm), top-4 + softmax ----
    float (*lg)[E_EXP + 1] = reinterpret_cast<float (*)[E_EXP + 1]>(&xsm[0][0]);
    #pragma unroll
    for (int j = 0; j < 4; ++j) {
        const int e = 8 * j + 2 * tig;
        lg[wo + gid][e]         = acc[j][0];
        lg[wo + gid][e + 1]     = acc[j][1];
        lg[wo + gid + 8][e]     = acc[j][2];
        lg[wo + gid + 8][e + 1] = acc[j][3];
    }
    __syncthreads();

    if (tid < BM) {
        const int t = tid;
        float bv0 = -1e30f, bv1 = -1e30f, bv2 = -1e30f, bv3 = -1e30f;
        int   bi0 = 0, bi1 = 0, bi2 = 0, bi3 = 0;
        #pragma unroll
        for (int e = 0; e < E_EXP; ++e) {
            float lv = lg[t][e] + bias[e];
            if (lv > bv3) {
                if (lv > bv0) {
                    bv3 = bv2; bi3 = bi2; bv2 = bv1; bi2 = bi1; bv1 = bv0; bi1 = bi0;
                    bv0 = lv;  bi0 = e;
                } else if (lv > bv1) {
                    bv3 = bv2; bi3 = bi2; bv2 = bv1; bi2 = bi1;
                    bv1 = lv;  bi1 = e;
                } else if (lv > bv2) {
                    bv3 = bv2; bi3 = bi2;
                    bv2 = lv;  bi2 = e;
                } else {
                    bv3 = lv;  bi3 = e;
                }
            }
        }
        float e0 = 1.0f;
        float e1 = expf(bv1 - bv0);
        float e2 = expf(bv2 - bv0);
        float e3 = expf(bv3 - bv0);
        float inv = 1.0f / (e0 + e1 + e2 + e3);

        const int gt = t0 + t;
        float* oi = out + (size_t)gt * TOPK;
        float* ow = out + (size_t)T_TOKENS * TOPK + (size_t)gt * TOPK;
        oi[0] = (float)bi0; oi[1] = (float)bi1; oi[2] = (float)bi2; oi[3] = (float)bi3;
        ow[0] = e0 * inv;   ow[1] = e1 * inv;   ow[2] = e2 * inv;   ow[3] = e3 * inv;
    }
}

extern "C" void kernel_launch(void* const* d_in, const int* in_sizes, int n_in,
                              void* d_out, int out_size)
{
    const float* x    = (const float*)d_in[0];  // [4,4096,2880] f32
    const float* w    = (const float*)d_in[1];  // [32,2880] f32
    const float* bias = (const float*)d_in[2];  // [32] f32
    float* out = (float*)d_out;

    convert_w<<<(E_EXP * H_DIM + 255) / 256, 256>>>(w);
    gate_mma<<<T_TOKENS / BM, NTHREADS>>>(x, bias, out);   // 256 CTAs x 4 warps, all co-resident
}

// round 10
// speedup vs baseline: 2.6866x; 1.0087x over previous
#include <cuda_runtime.h>
#include <cuda_bf16.h>

#define T_TOKENS 16384
#define H_DIM    2880
#define E_EXP    32
#define TOPK     4
#define BM       64
#define KPW      (H_DIM / 4)        // 720 per warp
#define NST      (KPW / 16)         // 45 stages of k16 per warp
#define NTHREADS 128

// W bf16 hi/lo planes, k-INTERLEAVED within each 16-group so one LDS.64 = (b0,b1) frag:
// pos(k) within 16: {0,1,8,9, 2,3,10,11, 4,5,12,13, 6,7,14,15}
__device__ __nv_bfloat16 g_wh[E_EXP * H_DIM];
__device__ __nv_bfloat16 g_wl[E_EXP * H_DIM];

__global__ __launch_bounds__(256)
void convert_w(const float* __restrict__ w)
{
    int i = blockIdx.x * 256 + threadIdx.x;
    if (i < E_EXP * H_DIM) {
        int k   = i % H_DIM;
        int kb  = k & ~15;
        int k16 = k & 15;
        int pos = ((k16 & 7) >> 1) * 4 + ((k16 >> 3) << 1) + (k16 & 1);
        int j   = i - k + kb + pos;
        float v = w[i];
        __nv_bfloat16 h = __float2bfloat16_rn(v);
        g_wh[j] = h;
        g_wl[j] = __float2bfloat16_rn(v - __bfloat162float(h));
    }
}

__device__ __forceinline__ unsigned smem_u32(const void* p) {
    return (unsigned)__cvta_generic_to_shared(p);
}
__device__ __forceinline__ void cp16(unsigned dst, const void* src) {
    asm volatile("cp.async.cg.shared.global [%0], [%1], 16;" :: "r"(dst), "l"(src));
}
__device__ __forceinline__ void cp_commit() {
    asm volatile("cp.async.commit_group;");
}
template <int N>
__device__ __forceinline__ void cp_wait() {
    asm volatile("cp.async.wait_group %0;" :: "n"(N));
}
__device__ __forceinline__ void cvt_hl(float2 f, unsigned& h, unsigned& l)
{
    asm("cvt.rn.bf16x2.f32 %0, %1, %2;" : "=r"(h) : "f"(f.y), "f"(f.x));
    float h0 = __uint_as_float(h << 16);
    float h1 = __uint_as_float(h & 0xffff0000u);
    asm("cvt.rn.bf16x2.f32 %0, %1, %2;" : "=r"(l) : "f"(f.y - h1), "f"(f.x - h0));
}
__device__ __forceinline__ void hmma(float* d, const unsigned* a, unsigned b0, unsigned b1)
{
    asm volatile(
        "mma.sync.aligned.m16n8k16.row.col.f32.bf16.bf16.f32 "
        "{%0,%1,%2,%3}, {%4,%5,%6,%7}, {%8,%9}, {%0,%1,%2,%3};"
        : "+f"(d[0]), "+f"(d[1]), "+f"(d[2]), "+f"(d[3])
        : "r"(a[0]), "r"(a[1]), "r"(a[2]), "r"(a[3]), "r"(b0), "r"(b1));
}

__global__ __launch_bounds__(NTHREADS, 3)
void gate_mma(const float* __restrict__ x,
              const float* __restrict__ bias,
              float* __restrict__ out)
{
    // Shared buffers, but warp-private COLUMN regions (warp w owns x-chunks 4w..4w+3,
    // w-chunks 2w..2w+1, pre-XOR). Swizzles are bijective per row -> regions disjoint.
    __shared__ __align__(16) char xsm[3][BM * 256];        // 48 KB  (x: [tok][16 chunks])
    __shared__ __align__(16) char wsm[3][2 * E_EXP * 128]; // 24 KB  (w: [pl][e][8 chunks])

    const int tid  = threadIdx.x;
    const int warp = tid >> 5;
    const int lane = tid & 31;
    const int gid  = lane >> 2;       // 0..7
    const int tig  = lane & 3;        // 0..3
    const int t0   = blockIdx.x * BM;
    const int kb   = warp * KPW;      // this warp's K base

    // ---- warp-private staging maps ----
    // x: 256 chunks/stage (64 tok x 4 chunks): id = lane + 32*i (i<8): tok=id>>2, kc=id&3
    const float* xsrc[8];
    int xdo[8];
    #pragma unroll
    for (int i = 0; i < 8; ++i) {
        int id  = lane + 32 * i;
        int tok = id >> 2, kc = id & 3;
        xsrc[i] = x + (size_t)(t0 + tok) * H_DIM + kb + kc * 4;
        xdo[i]  = tok * 256 + (((4 * warp + kc) ^ (tok & 7)) << 4);
    }
    // w: 128 chunks/stage (2 pl x 32 e x 2 chunks): id = lane + 32*i (i<4): pl=id>>6, e=(id>>1)&31, h=id&1
    const __nv_bfloat16* wsrc[4];
    int wdo[4];
    #pragma unroll
    for (int i = 0; i < 4; ++i) {
        int id = lane + 32 * i;
        int pl = id >> 6, e = (id >> 1) & 31, h = id & 1;
        wsrc[i] = (pl ? g_wl : g_wh) + (size_t)e * H_DIM + kb + h * 8;
        wdo[i]  = pl * 4096 + e * 128 + (((2 * warp + h) ^ (e & 7)) << 4);
    }

    auto stage = [&](int s, int b) {
        const size_t ko = (size_t)s * 16;
        #pragma unroll
        for (int i = 0; i < 8; ++i)
            cp16(smem_u32(&xsm[b][xdo[i]]), xsrc[i] + ko);
        #pragma unroll
        for (int i = 0; i < 4; ++i)
            cp16(smem_u32(&wsm[b][wdo[i]]), wsrc[i] + ko);
        cp_commit();
    };

    // ---- compute-side constants ----
    const int cl  = tig >> 1;
    const int sub = (tig & 1) * 8;
    const int cA0 = (((4 * warp + cl)     ^ gid) << 4) + sub;   // k-low chunk byte offset
    const int cA1 = (((4 * warp + cl + 2) ^ gid) << 4) + sub;   // k-high
    const int cB  = (((2 * warp + cl)     ^ gid) << 4) + sub;

    // acc[m][j]: token tile m (rows m*16+gid, +8), expert 8j+gid
    float acc[4][4][4];
    #pragma unroll
    for (int m = 0; m < 4; ++m)
        #pragma unroll
        for (int j = 0; j < 4; ++j)
            #pragma unroll
            for (int q = 0; q < 4; ++q) acc[m][j][q] = 0.0f;

    stage(0, 0);
    stage(1, 1);

    for (int s = 0; s < NST; ++s) {
        if (s + 2 < NST) { stage(s + 2, (s + 2) % 3); cp_wait<2>(); }
        else if (s + 1 < NST) { cp_wait<1>(); }
        else { cp_wait<0>(); }
        __syncwarp();                 // warp-scope visibility; NO block barrier

        const char* xb = xsm[s % 3];
        const char* wb = wsm[s % 3];

        // B fragments for this warp's k16 (hoisted: shared by all 4 token tiles)
        uint2 bh[4], bl[4];
        #pragma unroll
        for (int j = 0; j < 4; ++j) {
            const int e = 8 * j + gid;
            bh[j] = *reinterpret_cast<const uint2*>(wb + e * 128 + cB);
            bl[j] = *reinterpret_cast<const uint2*>(wb + 4096 + e * 128 + cB);
        }

        #pragma unroll
        for (int m = 0; m < 4; ++m) {
            const int r0 = m * 16 + gid, r1 = r0 + 8;
            float2 f00 = *reinterpret_cast<const float2*>(xb + r0 * 256 + cA0);
            float2 f10 = *reinterpret_cast<const float2*>(xb + r1 * 256 + cA0);
            float2 f01 = *reinterpret_cast<const float2*>(xb + r0 * 256 + cA1);
            float2 f11 = *reinterpret_cast<const float2*>(xb + r1 * 256 + cA1);
            unsigned ah[4], al[4];
            cvt_hl(f00, ah[0], al[0]);
            cvt_hl(f10, ah[1], al[1]);
            cvt_hl(f01, ah[2], al[2]);
            cvt_hl(f11, ah[3], al[3]);

            #pragma unroll
            for (int j = 0; j < 4; ++j) {
                hmma(acc[m][j], ah, bh[j].x, bh[j].y);
                hmma(acc[m][j], al, bh[j].x, bh[j].y);
                hmma(acc[m][j], ah, bl[j].x, bl[j].y);
            }
        }
        __syncwarp();                 // reads of buffer s done before lanes re-stage it
    }

    // ---- cross-warp K reduction: partial logits to smem ----
    float (*part)[BM][E_EXP] = reinterpret_cast<float (*)[BM][E_EXP]>(&xsm[0][0]); // 32KB
    __syncthreads();                  // mainloop smem reads done in ALL warps before aliasing
    #pragma unroll
    for (int m = 0; m < 4; ++m)
        #pragma unroll
        for (int j = 0; j < 4; ++j) {
            const int e = 8 * j + 2 * tig;
            part[warp][m * 16 + gid][e]         = acc[m][j][0];
            part[warp][m * 16 + gid][e + 1]     = acc[m][j][1];
            part[warp][m * 16 + gid + 8][e]     = acc[m][j][2];
            part[warp][m * 16 + gid + 8][e + 1] = acc[m][j][3];
        }
    __syncthreads();

    if (tid < BM) {
        const int t = tid;
        float bv0 = -1e30f, bv1 = -1e30f, bv2 = -1e30f, bv3 = -1e30f;
        int   bi0 = 0, bi1 = 0, bi2 = 0, bi3 = 0;
        #pragma unroll
        for (int e = 0; e < E_EXP; ++e) {
            float lv = part[0][t][e] + part[1][t][e] + part[2][t][e] + part[3][t][e]
                     + bias[e];
            if (lv > bv3) {
                if (lv > bv0) {
                    bv3 = bv2; bi3 = bi2; bv2 = bv1; bi2 = bi1; bv1 = bv0; bi1 = bi0;
                    bv0 = lv;  bi0 = e;
                } else if (lv > bv1) {
                    bv3 = bv2; bi3 = bi2; bv2 = bv1; bi2 = bi1;
                    bv1 = lv;  bi1 = e;
                } else if (lv > bv2) {
                    bv3 = bv2; bi3 = bi2;
                    bv2 = lv;  bi2 = e;
                } else {
                    bv3 = lv;  bi3 = e;
                }
            }
        }
        float e0 = 1.0f;
        float e1 = expf(bv1 - bv0);
        float e2 = expf(bv2 - bv0);
        float e3 = expf(bv3 - bv0);
        float inv = 1.0f / (e0 + e1 + e2 + e3);

        const int gt = t0 + t;
        float* oi = out + (size_t)gt * TOPK;
        float* ow = out + (size_t)T_TOKENS * TOPK + (size_t)gt * TOPK;
        oi[0] = (float)bi0; oi[1] = (float)bi1; oi[2] = (float)bi2; oi[3] = (float)bi3;
        ow[0] = e0 * inv;   ow[1] = e1 * inv;   ow[2] = e2 * inv;   ow[3] = e3 * inv;
    }
}

extern "C" void kernel_launch(void* const* d_in, const int* in_sizes, int n_in,
                              void* d_out, int out_size)
{
    const float* x    = (const float*)d_in[0];  // [4,4096,2880] f32
    const float* w    = (const float*)d_in[1];  // [32,2880] f32
    const float* bias = (const float*)d_in[2];  // [32] f32
    float* out = (float*)d_out;

    convert_w<<<(E_EXP * H_DIM + 255) / 256, 256>>>(w);
    gate_mma<<<T_TOKENS / BM, NTHREADS>>>(x, bias, out);   // 256 CTAs x 4 warps (warp-K-split)
}